// round 12
// baseline (speedup 1.0000x reference)
#include <cuda_runtime.h>
#include <cuda_bf16.h>
#include <cstdint>

// ShortConv: causal depthwise Conv1d (K=4) + SiLU.
// x: (B=4, L=4096, D=2048) fp32, D contiguous. w: (D, 1, 4) fp32.
// y[b,l,d] = silu( sum_{k=0..3} w[d,0,k] * x[b, l-3+k, d] ), OOB x -> 0.
//
// R11 vs R10-best (51.2-51.6us, ncu 42.0, DRAM 65%, occ 48%):
//  Hypothesis: occupancy is still the open lever, but only spill-free.
//  RF caps threads at 64K/48regs = 1365 -> occ 5. Shed the 12 window regs by
//  reading the full 4-row window from the smem ring (rows i-3..i are still
//  there): 4x LDS.128/row instead of 1 (+12 LSU cyc, MIO at ~45% has room),
//  iterations become independent, state drops to ~40-42 regs ->
//  __launch_bounds__(256,6) satisfiable WITHOUT R9's pipeline collapse.
//  Ring: preloads -> stages 5,6,7; cp.async depth 4 (wait_group 3);
//  write stage (i+4)&7 vs read (i-3..i)&7 disjoint. No barriers (columns
//  thread-private). NCTAS = 888 = 148 x 6.

#define DIM        2048
#define D4         (DIM / 4)       // 512 float4 per row
#define SEQLEN     4096
#define BATCH      4
#define THREADS    256
#define DGROUPS    (D4 / THREADS)  // 2
#define NCOLS      (BATCH * DGROUPS)          // 8
#define TOTAL_ROWS (NCOLS * SEQLEN)           // 32768
#define NCTAS      888                        // 148 SMs x occ 6
#define STAGES     8
#define STAGE_BYTES (THREADS * 16)            // 4KB per stage

__device__ __forceinline__ void cp_async16(uint32_t dst_smem, const void* src) {
    asm volatile("cp.async.cg.shared.global [%0], [%1], 16;\n"
                 :: "r"(dst_smem), "l"(src));
}
__device__ __forceinline__ void cp_commit() {
    asm volatile("cp.async.commit_group;\n");
}
__device__ __forceinline__ void cp_wait3() {  // wait until <= 3 groups pending
    asm volatile("cp.async.wait_group 3;\n");
}

__device__ __forceinline__ float silu1(float v) {
    // silu(v) = 0.5*v*(1 + tanh(v/2)); tanh.approx = 1 MUFU.
    float t, h = 0.5f * v;
    asm("tanh.approx.f32 %0, %1;" : "=f"(t) : "f"(h));
    return fmaf(h, t, h);
}

__global__ __launch_bounds__(THREADS, 6)
void shortconv_silu_kernel(const float4* __restrict__ x,
                           const float4* __restrict__ w4,
                           float4* __restrict__ y) {
    __shared__ float4 ring[STAGES][THREADS];

    const uint32_t ring_base =
        (uint32_t)__cvta_generic_to_shared(&ring[0][threadIdx.x]);

    const unsigned int cta = blockIdx.x;
    unsigned int r0 = (unsigned int)(((unsigned long long)cta       * TOTAL_ROWS) / NCTAS);
    const unsigned int r1 = (unsigned int)(((unsigned long long)(cta + 1) * TOTAL_ROWS) / NCTAS);

    const float4 zero = make_float4(0.f, 0.f, 0.f, 0.f);

    while (r0 < r1) {
        const unsigned int c = r0 >> 12;            // column: b*DGROUPS + dg
        const unsigned int l = r0 & (SEQLEN - 1);   // row within column
        const unsigned int seg_end = min(r1, (c + 1) << 12);
        const int n = (int)(seg_end - r0);

        const int dg = c & (DGROUPS - 1);
        const int b  = c >> 1;
        const int d4 = dg * THREADS + threadIdx.x;

        // Channel taps: w floats are [d*4+k]; this lane's 4 channels = 4 contiguous float4.
        const float4 wa = w4[d4 * 4 + 0];
        const float4 wb = w4[d4 * 4 + 1];
        const float4 wc = w4[d4 * 4 + 2];
        const float4 wd = w4[d4 * 4 + 3];

        const float4* xp = x + ((size_t)b * SEQLEN + l) * D4 + d4;
        float4*       yp = y + ((size_t)b * SEQLEN + l) * D4 + d4;

        // Causal preload: rows l-3,l-2,l-1 into ring stages 5,6,7 ((-3..-1)&7).
        // Thread-private slots; same-thread st.shared -> ld.shared is ordered.
        ring[5][threadIdx.x] = (l >= 3) ? __ldcs(xp - 3 * D4) : zero;
        ring[6][threadIdx.x] = (l >= 2) ? __ldcs(xp - 2 * D4) : zero;
        ring[7][threadIdx.x] = (l >= 1) ? __ldcs(xp - 1 * D4) : zero;

        // Prologue: issue rows 0..3 into stages 0..3 (guarded), one group each.
        #pragma unroll
        for (int s = 0; s < 4; ++s) {
            if (s < n) cp_async16(ring_base + s * STAGE_BYTES, xp + s * D4);
            cp_commit();
        }

        #pragma unroll 2
        for (int i = 0; i < n; ++i) {
            cp_wait3();                            // row i's group complete

            // Full 4-row window from the ring (no register carry).
            const float4 xc  = ring[ i      & (STAGES - 1)][threadIdx.x];
            const float4 xm1 = ring[(i + 7) & (STAGES - 1)][threadIdx.x];
            const float4 xm2 = ring[(i + 6) & (STAGES - 1)][threadIdx.x];
            const float4 xm3 = ring[(i + 5) & (STAGES - 1)][threadIdx.x];

            // Refill: row i+4 into stage (i+4)&7 (disjoint from read window).
            const int il = i + 4;
            if (il < n)
                cp_async16(ring_base + (il & (STAGES - 1)) * STAGE_BYTES, xp + il * D4);
            cp_commit();

            float4 r;
            r.x = fmaf(wa.x, xm3.x, fmaf(wa.y, xm2.x, fmaf(wa.z, xm1.x, wa.w * xc.x)));
            r.y = fmaf(wb.x, xm3.y, fmaf(wb.y, xm2.y, fmaf(wb.z, xm1.y, wb.w * xc.y)));
            r.z = fmaf(wc.x, xm3.z, fmaf(wc.y, xm2.z, fmaf(wc.z, xm1.z, wc.w * xc.z)));
            r.w = fmaf(wd.x, xm3.w, fmaf(wd.y, xm2.w, fmaf(wd.z, xm1.w, wd.w * xc.w)));

            r.x = silu1(r.x);
            r.y = silu1(r.y);
            r.z = silu1(r.z);
            r.w = silu1(r.w);

            __stcs(yp + i * D4, r);
        }

        r0 = seg_end;
    }
}

extern "C" void kernel_launch(void* const* d_in, const int* in_sizes, int n_in,
                              void* d_out, int out_size) {
    const float4* x  = (const float4*)d_in[0];
    const float4* w4 = (const float4*)d_in[1];
    float4*       y  = (float4*)d_out;

    shortconv_silu_kernel<<<NCTAS, THREADS>>>(x, w4, y);
}

// round 13
// speedup vs baseline: 1.0704x; 1.0704x over previous
#include <cuda_runtime.h>
#include <cuda_bf16.h>
#include <cstdint>

// ShortConv: causal depthwise Conv1d (K=4) + SiLU.
// x: (B=4, L=4096, D=2048) fp32, D contiguous. w: (D, 1, 4) fp32.
// y[b,l,d] = silu( sum_{k=0..3} w[d,0,k] * x[b, l-3+k, d] ), OOB x -> 0.
//
// FINAL: R6/R10 configuration — the measured optimum, reproduced 3x
// (ncu 42.0us; bench 51.2/51.6/53.1, ±2us harness noise).
//
// Optimization history / evidence for the plateau:
//  R1  baseline float4 sliding window            71.7us (occ 42%, latency-bound)
//  R2  occ cap 5, instr diet, tanh-silu          65.5us
//  R4  balanced persistent CTAs (740, row-split) 54.9us (occ 58% -> balance solved)
//  R6  cp.async depth-7 smem ring (this config)  51.2us (DRAM 65%, 5.33 TB/s)
//  R8  paired groups, depth 8: ncu IDENTICAL  -> instr mix/depth saturated
//  R9  occ 6 by forcing regs 48->40: 2x SLOWER -> pipeline collapse
//  R11 occ 6 by smem-window (regs 40 clean): occ 53%, DRAM same, slightly worse
//     -> occupancy is not the binder; ~6.2 TB/s logical (~78% spec) is the
//        practical ceiling for this mixed read+write stream. Remaining levers
//        (write batching) need regs/smem beyond the 5-CTA/SM boundary and are
//        strictly dominated.

#define DIM        2048
#define D4         (DIM / 4)       // 512 float4 per row
#define SEQLEN     4096
#define BATCH      4
#define THREADS    256
#define DGROUPS    (D4 / THREADS)  // 2
#define NCOLS      (BATCH * DGROUPS)          // 8
#define TOTAL_ROWS (NCOLS * SEQLEN)           // 32768
#define NCTAS      740                        // 148 SMs x occ 5
#define STAGES     8
#define STAGE_BYTES (THREADS * 16)            // 4KB per stage

__device__ __forceinline__ void cp_async16(uint32_t dst_smem, const void* src) {
    asm volatile("cp.async.cg.shared.global [%0], [%1], 16;\n"
                 :: "r"(dst_smem), "l"(src));
}
__device__ __forceinline__ void cp_commit() {
    asm volatile("cp.async.commit_group;\n");
}
__device__ __forceinline__ void cp_wait_allbutN() {  // wait until <= STAGES-2 pending
    asm volatile("cp.async.wait_group %0;\n" :: "n"(STAGES - 2));
}

__device__ __forceinline__ float silu1(float v) {
    // silu(v) = 0.5*v*(1 + tanh(v/2)); tanh.approx = 1 MUFU.
    float t, h = 0.5f * v;
    asm("tanh.approx.f32 %0, %1;" : "=f"(t) : "f"(h));
    return fmaf(h, t, h);
}

__global__ __launch_bounds__(THREADS, 5)
void shortconv_silu_kernel(const float4* __restrict__ x,
                           const float4* __restrict__ w4,
                           float4* __restrict__ y) {
    __shared__ float4 ring[STAGES][THREADS];

    const uint32_t ring_base =
        (uint32_t)__cvta_generic_to_shared(&ring[0][threadIdx.x]);

    const unsigned int cta = blockIdx.x;
    unsigned int r0 = (unsigned int)(((unsigned long long)cta       * TOTAL_ROWS) / NCTAS);
    const unsigned int r1 = (unsigned int)(((unsigned long long)(cta + 1) * TOTAL_ROWS) / NCTAS);

    const float4 zero = make_float4(0.f, 0.f, 0.f, 0.f);

    while (r0 < r1) {
        const unsigned int c = r0 >> 12;            // column: b*DGROUPS + dg
        const unsigned int l = r0 & (SEQLEN - 1);   // row within column
        const unsigned int seg_end = min(r1, (c + 1) << 12);
        const int n = (int)(seg_end - r0);

        const int dg = c & (DGROUPS - 1);
        const int b  = c >> 1;
        const int d4 = dg * THREADS + threadIdx.x;

        // Channel taps: w floats are [d*4+k]; this lane's 4 channels = 4 contiguous float4.
        const float4 wa = w4[d4 * 4 + 0];
        const float4 wb = w4[d4 * 4 + 1];
        const float4 wc = w4[d4 * 4 + 2];
        const float4 wd = w4[d4 * 4 + 3];

        const float4* xp = x + ((size_t)b * SEQLEN + l) * D4 + d4;
        float4*       yp = y + ((size_t)b * SEQLEN + l) * D4 + d4;

        // Causal window preload (overlaps with pipeline prologue).
        float4 xm3 = (l >= 3) ? __ldcs(xp - 3 * D4) : zero;
        float4 xm2 = (l >= 2) ? __ldcs(xp - 2 * D4) : zero;
        float4 xm1 = (l >= 1) ? __ldcs(xp - 1 * D4) : zero;

        // Pipeline prologue: issue rows 0..STAGES-2 (guarded), one group each.
        #pragma unroll
        for (int s = 0; s < STAGES - 1; ++s) {
            if (s < n) cp_async16(ring_base + s * STAGE_BYTES, xp + s * D4);
            cp_commit();
        }

        #pragma unroll 2
        for (int i = 0; i < n; ++i) {
            cp_wait_allbutN();                     // row i's group complete
            const float4 xc = ring[i & (STAGES - 1)][threadIdx.x];

            // Refill: row i+STAGES-1 into the stage freed last iteration.
            const int il = i + (STAGES - 1);
            if (il < n)
                cp_async16(ring_base + (il & (STAGES - 1)) * STAGE_BYTES, xp + il * D4);
            cp_commit();

            float4 r;
            r.x = fmaf(wa.x, xm3.x, fmaf(wa.y, xm2.x, fmaf(wa.z, xm1.x, wa.w * xc.x)));
            r.y = fmaf(wb.x, xm3.y, fmaf(wb.y, xm2.y, fmaf(wb.z, xm1.y, wb.w * xc.y)));
            r.z = fmaf(wc.x, xm3.z, fmaf(wc.y, xm2.z, fmaf(wc.z, xm1.z, wc.w * xc.z)));
            r.w = fmaf(wd.x, xm3.w, fmaf(wd.y, xm2.w, fmaf(wd.z, xm1.w, wd.w * xc.w)));

            r.x = silu1(r.x);
            r.y = silu1(r.y);
            r.z = silu1(r.z);
            r.w = silu1(r.w);

            __stcs(yp + i * D4, r);

            xm3 = xm2; xm2 = xm1; xm1 = xc;
        }

        r0 = seg_end;
    }
}

extern "C" void kernel_launch(void* const* d_in, const int* in_sizes, int n_in,
                              void* d_out, int out_size) {
    const float4* x  = (const float4*)d_in[0];
    const float4* w4 = (const float4*)d_in[1];
    float4*       y  = (float4*)d_out;

    shortconv_silu_kernel<<<NCTAS, THREADS>>>(x, w4, y);
}

// round 16
// speedup vs baseline: 1.0737x; 1.0031x over previous
#include <cuda_runtime.h>
#include <cuda_bf16.h>
#include <cstdint>

// ShortConv: causal depthwise Conv1d (K=4) + SiLU.
// x: (B=4, L=4096, D=2048) fp32, D contiguous. w: (D, 1, 4) fp32.
// y[b,l,d] = silu( sum_{k=0..3} w[d,0,k] * x[b, l-3+k, d] ), OOB x -> 0.
//
// FINAL: R6/R10/R12 configuration — measured optimum, reproduced 4x
// (bench 51.2/51.6/53.1/51.4us; ncu 42.0us, DRAM 65%, 5.33 TB/s,
//  ~6.2 TB/s logical ~ 78% of spec for this mixed read+write stream).
//
// Evidence for the plateau (all levers tested):
//  R8  paired cp.async groups, depth 8: ncu IDENTICAL -> mix/depth saturated.
//  R9  occ 6 by forcing regs 48->40: 2x slower (pipeline collapse).
//  R11 occ 6 via smem-window (regs 40 clean): occ 53%, DRAM same, slightly
//      worse -> occupancy not the binder.
//  R13/R14 bulk (TMA) write batching: killed the container twice (hang
//      suspected in bulk-group waits under harness capture) -> abandoned;
//      upside was ~10% against a 4x-reproduced plateau.

#define DIM        2048
#define D4         (DIM / 4)       // 512 float4 per row
#define SEQLEN     4096
#define BATCH      4
#define THREADS    256
#define DGROUPS    (D4 / THREADS)  // 2
#define NCOLS      (BATCH * DGROUPS)          // 8
#define TOTAL_ROWS (NCOLS * SEQLEN)           // 32768
#define NCTAS      740                        // 148 SMs x occ 5
#define STAGES     8
#define STAGE_BYTES (THREADS * 16)            // 4KB per stage

__device__ __forceinline__ void cp_async16(uint32_t dst_smem, const void* src) {
    asm volatile("cp.async.cg.shared.global [%0], [%1], 16;\n"
                 :: "r"(dst_smem), "l"(src));
}
__device__ __forceinline__ void cp_commit() {
    asm volatile("cp.async.commit_group;\n");
}
__device__ __forceinline__ void cp_wait_allbutN() {  // wait until <= STAGES-2 pending
    asm volatile("cp.async.wait_group %0;\n" :: "n"(STAGES - 2));
}

__device__ __forceinline__ float silu1(float v) {
    // silu(v) = 0.5*v*(1 + tanh(v/2)); tanh.approx = 1 MUFU.
    float t, h = 0.5f * v;
    asm("tanh.approx.f32 %0, %1;" : "=f"(t) : "f"(h));
    return fmaf(h, t, h);
}

__global__ __launch_bounds__(THREADS, 5)
void shortconv_silu_kernel(const float4* __restrict__ x,
                           const float4* __restrict__ w4,
                           float4* __restrict__ y) {
    __shared__ float4 ring[STAGES][THREADS];

    const uint32_t ring_base =
        (uint32_t)__cvta_generic_to_shared(&ring[0][threadIdx.x]);

    const unsigned int cta = blockIdx.x;
    unsigned int r0 = (unsigned int)(((unsigned long long)cta       * TOTAL_ROWS) / NCTAS);
    const unsigned int r1 = (unsigned int)(((unsigned long long)(cta + 1) * TOTAL_ROWS) / NCTAS);

    const float4 zero = make_float4(0.f, 0.f, 0.f, 0.f);

    while (r0 < r1) {
        const unsigned int c = r0 >> 12;            // column: b*DGROUPS + dg
        const unsigned int l = r0 & (SEQLEN - 1);   // row within column
        const unsigned int seg_end = min(r1, (c + 1) << 12);
        const int n = (int)(seg_end - r0);

        const int dg = c & (DGROUPS - 1);
        const int b  = c >> 1;
        const int d4 = dg * THREADS + threadIdx.x;

        // Channel taps: w floats are [d*4+k]; this lane's 4 channels = 4 contiguous float4.
        const float4 wa = w4[d4 * 4 + 0];
        const float4 wb = w4[d4 * 4 + 1];
        const float4 wc = w4[d4 * 4 + 2];
        const float4 wd = w4[d4 * 4 + 3];

        const float4* xp = x + ((size_t)b * SEQLEN + l) * D4 + d4;
        float4*       yp = y + ((size_t)b * SEQLEN + l) * D4 + d4;

        // Causal window preload (overlaps with pipeline prologue).
        float4 xm3 = (l >= 3) ? __ldcs(xp - 3 * D4) : zero;
        float4 xm2 = (l >= 2) ? __ldcs(xp - 2 * D4) : zero;
        float4 xm1 = (l >= 1) ? __ldcs(xp - 1 * D4) : zero;

        // Pipeline prologue: issue rows 0..STAGES-2 (guarded), one group each.
        #pragma unroll
        for (int s = 0; s < STAGES - 1; ++s) {
            if (s < n) cp_async16(ring_base + s * STAGE_BYTES, xp + s * D4);
            cp_commit();
        }

        #pragma unroll 2
        for (int i = 0; i < n; ++i) {
            cp_wait_allbutN();                     // row i's group complete
            const float4 xc = ring[i & (STAGES - 1)][threadIdx.x];

            // Refill: row i+STAGES-1 into the stage freed last iteration.
            const int il = i + (STAGES - 1);
            if (il < n)
                cp_async16(ring_base + (il & (STAGES - 1)) * STAGE_BYTES, xp + il * D4);
            cp_commit();

            float4 r;
            r.x = fmaf(wa.x, xm3.x, fmaf(wa.y, xm2.x, fmaf(wa.z, xm1.x, wa.w * xc.x)));
            r.y = fmaf(wb.x, xm3.y, fmaf(wb.y, xm2.y, fmaf(wb.z, xm1.y, wb.w * xc.y)));
            r.z = fmaf(wc.x, xm3.z, fmaf(wc.y, xm2.z, fmaf(wc.z, xm1.z, wc.w * xc.z)));
            r.w = fmaf(wd.x, xm3.w, fmaf(wd.y, xm2.w, fmaf(wd.z, xm1.w, wd.w * xc.w)));

            r.x = silu1(r.x);
            r.y = silu1(r.y);
            r.z = silu1(r.z);
            r.w = silu1(r.w);

            __stcs(yp + i * D4, r);

            xm3 = xm2; xm2 = xm1; xm1 = xc;
        }

        r0 = seg_end;
    }
}

extern "C" void kernel_launch(void* const* d_in, const int* in_sizes, int n_in,
                              void* d_out, int out_size) {
    const float4* x  = (const float4*)d_in[0];
    const float4* w4 = (const float4*)d_in[1];
    float4*       y  = (float4*)d_out;

    shortconv_silu_kernel<<<NCTAS, THREADS>>>(x, w4, y);
}